// round 2
// baseline (speedup 1.0000x reference)
#include <cuda_runtime.h>
#include <cuda_bf16.h>
#include <cstdint>

// ---------------------------------------------------------------------------
// RegionModel: B=128 images [3,256,256] -> per-sample region expert (R=8):
//   conv3x3 s2 (3->32) +bias+relu -> conv3x3 s2 (32->64) -> conv3x3 s2 (64->128)
//   -> global avg pool [128] -> fc [2]
// Direct conv, 8-output-channel register blocking per thread, weights in smem.
// region is int32 (JAX downcasts int64 without x64 mode).
// ---------------------------------------------------------------------------

#define B_   128
#define R_   8

// Scratch activations (device globals: allocation-guard safe)
__device__ float g_buf1[(size_t)B_ * 32 * 128 * 128];  // 256 MiB
__device__ float g_buf2[(size_t)B_ * 64 * 64 * 64];    // 128 MiB
__device__ float g_buf3[(size_t)B_ * 128 * 32 * 32];   //  64 MiB
__device__ float g_feat[(size_t)B_ * 128];

// ---------------------------------------------------------------------------
// conv 3x3, stride 2, pad 1, bias + ReLU.
// in : [B, CIN, 2*HOUT, 2*HOUT]
// W  : [R, COUT, CIN, 3, 3], Bias: [R, COUT]
// out: [B, COUT, HOUT, HOUT]
// ---------------------------------------------------------------------------
template <int CIN, int COUT, int HOUT, int COB>
__global__ void __launch_bounds__(256) conv_s2_k(
    const float* __restrict__ in, const float* __restrict__ W,
    const float* __restrict__ Bias, const int* __restrict__ region,
    float* __restrict__ out)
{
    constexpr int HIN = 2 * HOUT;
    const int b   = blockIdx.z;
    const int co0 = blockIdx.y * COB;
    const int sp  = blockIdx.x * 256 + threadIdx.x;   // HOUT*HOUT divisible by 256

    const int r = region[b] & (R_ - 1);               // bounded even if dtype surprises

    // Stage the COB channels' weights in shared memory
    __shared__ float ws[COB * CIN * 9];
    {
        const float* wg = W + (((size_t)r * COUT + co0) * CIN) * 9;
        for (int i = threadIdx.x; i < COB * CIN * 9; i += 256)
            ws[i] = wg[i];
    }
    __syncthreads();

    const int oy = sp / HOUT;
    const int ox = sp % HOUT;

    float acc[COB];
#pragma unroll
    for (int c = 0; c < COB; c++)
        acc[c] = Bias[r * COUT + co0 + c];

    const float* xb = in + (size_t)b * CIN * HIN * HIN;

    for (int ci = 0; ci < CIN; ci++) {
        const float* xc = xb + (size_t)ci * HIN * HIN;
#pragma unroll
        for (int ky = 0; ky < 3; ky++) {
            const int iy = 2 * oy - 1 + ky;
            if ((unsigned)iy < (unsigned)HIN) {
                const float* xr = xc + (size_t)iy * HIN;
#pragma unroll
                for (int kx = 0; kx < 3; kx++) {
                    const int ix = 2 * ox - 1 + kx;
                    if ((unsigned)ix < (unsigned)HIN) {
                        const float x = __ldg(xr + ix);
                        const int wi = ci * 9 + ky * 3 + kx;
#pragma unroll
                        for (int c = 0; c < COB; c++)
                            acc[c] = fmaf(x, ws[c * CIN * 9 + wi], acc[c]);
                    }
                }
            }
        }
    }

    float* ob = out + ((size_t)b * COUT + co0) * (HOUT * HOUT) + sp;
#pragma unroll
    for (int c = 0; c < COB; c++)
        ob[(size_t)c * HOUT * HOUT] = fmaxf(acc[c], 0.0f);
}

// ---------------------------------------------------------------------------
// Global average pool: in [B,128,32,32] -> feat [B,128]. One block per (b,c).
// ---------------------------------------------------------------------------
__global__ void __launch_bounds__(256) gap_k(const float* __restrict__ in,
                                             float* __restrict__ feat)
{
    const int bc = blockIdx.x;                 // b*128 + c
    const float* p = in + (size_t)bc * 1024;
    const int t = threadIdx.x;

    float s = p[t] + p[t + 256] + p[t + 512] + p[t + 768];

    __shared__ float red[256];
    red[t] = s;
    __syncthreads();
#pragma unroll
    for (int off = 128; off >= 32; off >>= 1) {
        if (t < off) red[t] += red[t + off];
        __syncthreads();
    }
    if (t < 32) {
        float v = red[t];
#pragma unroll
        for (int off = 16; off > 0; off >>= 1)
            v += __shfl_down_sync(0xFFFFFFFFu, v, off);
        if (t == 0) feat[bc] = v * (1.0f / 1024.0f);
    }
}

// ---------------------------------------------------------------------------
// FC: out[b,k] = fw[r,k,:] @ feat[b,:] + fb[r,k].  One warp per b.
// fw: [R,2,128], fb: [R,2]
// ---------------------------------------------------------------------------
__global__ void __launch_bounds__(32) fc_k(const float* __restrict__ feat,
                                           const float* __restrict__ fw,
                                           const float* __restrict__ fb,
                                           const int* __restrict__ region,
                                           float* __restrict__ out)
{
    const int b = blockIdx.x;
    const int lane = threadIdx.x;
    const int r = region[b] & (R_ - 1);

    const float* fv = feat + (size_t)b * 128;
    const float* w0 = fw + ((size_t)r * 2 + 0) * 128;
    const float* w1 = fw + ((size_t)r * 2 + 1) * 128;

    float p0 = 0.0f, p1 = 0.0f;
#pragma unroll
    for (int i = lane; i < 128; i += 32) {
        const float f = fv[i];
        p0 = fmaf(f, w0[i], p0);
        p1 = fmaf(f, w1[i], p1);
    }
#pragma unroll
    for (int off = 16; off > 0; off >>= 1) {
        p0 += __shfl_down_sync(0xFFFFFFFFu, p0, off);
        p1 += __shfl_down_sync(0xFFFFFFFFu, p1, off);
    }
    if (lane == 0) {
        out[b * 2 + 0] = p0 + fb[r * 2 + 0];
        out[b * 2 + 1] = p1 + fb[r * 2 + 1];
    }
}

// ---------------------------------------------------------------------------
extern "C" void kernel_launch(void* const* d_in, const int* in_sizes, int n_in,
                              void* d_out, int out_size)
{
    const float* image  = (const float*)d_in[0];
    const int*   region = (const int*)d_in[1];
    const float* w1     = (const float*)d_in[2];
    const float* b1     = (const float*)d_in[3];
    const float* w2     = (const float*)d_in[4];
    const float* b2     = (const float*)d_in[5];
    const float* w3     = (const float*)d_in[6];
    const float* b3     = (const float*)d_in[7];
    const float* fw     = (const float*)d_in[8];
    const float* fb     = (const float*)d_in[9];
    float* out = (float*)d_out;

    float *buf1, *buf2, *buf3, *feat;
    cudaGetSymbolAddress((void**)&buf1, g_buf1);
    cudaGetSymbolAddress((void**)&buf2, g_buf2);
    cudaGetSymbolAddress((void**)&buf3, g_buf3);
    cudaGetSymbolAddress((void**)&feat, g_feat);

    // conv1: 3 -> 32, HOUT=128. spatial 16384 -> 64 blocks; 32/8 = 4 ch groups
    conv_s2_k<3, 32, 128, 8><<<dim3(64, 4, B_), 256>>>(image, w1, b1, region, buf1);
    // conv2: 32 -> 64, HOUT=64. spatial 4096 -> 16 blocks; 64/8 = 8 ch groups
    conv_s2_k<32, 64, 64, 8><<<dim3(16, 8, B_), 256>>>(buf1, w2, b2, region, buf2);
    // conv3: 64 -> 128, HOUT=32. spatial 1024 -> 4 blocks; 128/8 = 16 ch groups
    conv_s2_k<64, 128, 32, 8><<<dim3(4, 16, B_), 256>>>(buf2, w3, b3, region, buf3);
    // GAP: one block per (b, c)
    gap_k<<<B_ * 128, 256>>>(buf3, feat);
    // FC: one warp per sample
    fc_k<<<B_, 32>>>(feat, fw, fb, region, out);
}

// round 3
// speedup vs baseline: 1.7675x; 1.7675x over previous
#include <cuda_runtime.h>
#include <cuda_bf16.h>
#include <cstdint>

// ---------------------------------------------------------------------------
// RegionModel: B=128 images [3,256,256] -> per-sample region expert (R=8):
//   conv3x3 s2 (3->32) -> conv3x3 s2 (32->64) -> conv3x3 s2 (64->128)
//   (each +bias+ReLU) -> global avg pool [128] -> fc [2]
// Round-3: direct conv with packed f32x2 FMA (FFMA2), 16 output channels
// (8 packed pairs) x 8 pixels (2 rows x 4 cols) per thread, packed weights
// staged in smem (broadcast LDS.64). fp32 accuracy (fma.rn per lane).
// ---------------------------------------------------------------------------

#define B_   128
#define R_   8

// Scratch activations (device globals: allocation-guard safe)
__device__ float g_buf1[(size_t)B_ * 32 * 128 * 128];  // 256 MiB
__device__ float g_buf2[(size_t)B_ * 64 * 64 * 64];    // 128 MiB
__device__ float g_buf3[(size_t)B_ * 128 * 32 * 32];   //  64 MiB
__device__ float g_feat[(size_t)B_ * 128];

__device__ __forceinline__ unsigned long long pack2(float lo, float hi) {
    unsigned long long p;
    asm("mov.b64 %0, {%1, %2};" : "=l"(p) : "f"(lo), "f"(hi));
    return p;
}
__device__ __forceinline__ unsigned long long pack_dup(float x) {
    unsigned long long p;
    asm("mov.b64 %0, {%1, %1};" : "=l"(p) : "f"(x));
    return p;
}
__device__ __forceinline__ void unpack2(unsigned long long p, float& lo, float& hi) {
    asm("mov.b64 {%0, %1}, %2;" : "=f"(lo), "=f"(hi) : "l"(p));
}
#define FFMA2(acc, x, w) \
    asm("fma.rn.f32x2 %0, %1, %2, %0;" : "+l"(acc) : "l"(x), "l"(w))

// ---------------------------------------------------------------------------
// conv 3x3, stride 2, pad 1, bias + ReLU.
// in : [B, CIN, 2*HOUT, 2*HOUT]
// W  : [R, COUT, CIN, 3, 3], Bias: [R, COUT]
// out: [B, COUT, HOUT, HOUT]
// Thread: 16 output channels (8 f32x2 pairs) x (2 rows x 4 cols) pixels.
// Block: BLK threads over spatial tiles; blockIdx.y = channel group (16 ch);
// blockIdx.z = batch.
// ---------------------------------------------------------------------------
template <int CIN, int COUT, int HOUT, int BLK>
__global__ void __launch_bounds__(BLK) conv_s2_v2(
    const float* __restrict__ in, const float* __restrict__ W,
    const float* __restrict__ Bias, const int* __restrict__ region,
    float* __restrict__ out)
{
    constexpr int HIN = 2 * HOUT;
    constexpr int TX  = HOUT / 4;           // tile cols
    const int b   = blockIdx.z;
    const int co0 = blockIdx.y * 16;
    const int r   = region[b] & (R_ - 1);

    // Packed weights in smem: ws[(ci*9 + tap)*8 + c] = (W[co0+2c], W[co0+2c+1])
    __shared__ unsigned long long ws[CIN * 9 * 8];
    {
        const float* wg = W + ((size_t)r * COUT + co0) * CIN * 9;
        for (int idx = threadIdx.x; idx < CIN * 9 * 8; idx += BLK) {
            const int c = idx & 7, rest = idx >> 3;      // rest = ci*9+tap
            const float lo = wg[(size_t)(2 * c)     * CIN * 9 + rest];
            const float hi = wg[(size_t)(2 * c + 1) * CIN * 9 + rest];
            ws[idx] = pack2(lo, hi);
        }
    }
    __syncthreads();

    const int t   = blockIdx.x * BLK + threadIdx.x;
    const int ty  = t / TX;
    const int tx  = t % TX;
    const int oy0 = ty * 2;
    const int ox0 = tx * 4;

    // 64 packed accumulators = 16 ch x 8 px
    unsigned long long acc[2][4][8];
#pragma unroll
    for (int c = 0; c < 8; c++) {
        const unsigned long long bp =
            pack2(Bias[r * COUT + co0 + 2 * c], Bias[r * COUT + co0 + 2 * c + 1]);
#pragma unroll
        for (int py = 0; py < 2; py++)
#pragma unroll
            for (int px = 0; px < 4; px++)
                acc[py][px][c] = bp;
    }

    const float* xb = in + (size_t)b * CIN * HIN * HIN;

#pragma unroll 1
    for (int ci = 0; ci < CIN; ci++) {
        const float* xc = xb + (size_t)ci * HIN * HIN;
#pragma unroll
        for (int ky = 0; ky < 3; ky++) {
#pragma unroll
            for (int kx = 0; kx < 3; kx++) {
                // 8 packed weights for this tap (broadcast LDS.64)
                unsigned long long wv[8];
#pragma unroll
                for (int c = 0; c < 8; c++)
                    wv[c] = ws[(ci * 9 + ky * 3 + kx) * 8 + c];
#pragma unroll
                for (int py = 0; py < 2; py++) {
                    const int iy = 2 * (oy0 + py) + ky - 1;   // only -1 underflow possible
                    const float* xr = xc + (size_t)iy * HIN;
#pragma unroll
                    for (int px = 0; px < 4; px++) {
                        const int ix = 2 * (ox0 + px) + kx - 1;
                        float x = 0.0f;
                        if (iy >= 0 && ix >= 0) x = __ldg(xr + ix);
                        const unsigned long long xx = pack_dup(x);
#pragma unroll
                        for (int c = 0; c < 8; c++)
                            FFMA2(acc[py][px][c], xx, wv[c]);
                    }
                }
            }
        }
    }

    // ReLU + store: per (channel, row) a float4 over the 4 cols
#pragma unroll
    for (int c = 0; c < 8; c++) {
#pragma unroll
        for (int py = 0; py < 2; py++) {
            float lo0, hi0, lo1, hi1, lo2, hi2, lo3, hi3;
            unpack2(acc[py][0][c], lo0, hi0);
            unpack2(acc[py][1][c], lo1, hi1);
            unpack2(acc[py][2][c], lo2, hi2);
            unpack2(acc[py][3][c], lo3, hi3);
            float* o0 = out + (((size_t)b * COUT + co0 + 2 * c) * HOUT + oy0 + py) * HOUT + ox0;
            float* o1 = o0 + (size_t)HOUT * HOUT;
            *(float4*)o0 = make_float4(fmaxf(lo0, 0.f), fmaxf(lo1, 0.f),
                                       fmaxf(lo2, 0.f), fmaxf(lo3, 0.f));
            *(float4*)o1 = make_float4(fmaxf(hi0, 0.f), fmaxf(hi1, 0.f),
                                       fmaxf(hi2, 0.f), fmaxf(hi3, 0.f));
        }
    }
}

// ---------------------------------------------------------------------------
// Global average pool: in [B,128,32,32] -> feat [B,128]. One block per (b,c).
// ---------------------------------------------------------------------------
__global__ void __launch_bounds__(256) gap_k(const float* __restrict__ in,
                                             float* __restrict__ feat)
{
    const int bc = blockIdx.x;
    const float* p = in + (size_t)bc * 1024;
    const int t = threadIdx.x;

    float s = p[t] + p[t + 256] + p[t + 512] + p[t + 768];

    __shared__ float red[256];
    red[t] = s;
    __syncthreads();
#pragma unroll
    for (int off = 128; off >= 32; off >>= 1) {
        if (t < off) red[t] += red[t + off];
        __syncthreads();
    }
    if (t < 32) {
        float v = red[t];
#pragma unroll
        for (int off = 16; off > 0; off >>= 1)
            v += __shfl_down_sync(0xFFFFFFFFu, v, off);
        if (t == 0) feat[bc] = v * (1.0f / 1024.0f);
    }
}

// ---------------------------------------------------------------------------
// FC: out[b,k] = fw[r,k,:] @ feat[b,:] + fb[r,k].  One warp per b.
// ---------------------------------------------------------------------------
__global__ void __launch_bounds__(32) fc_k(const float* __restrict__ feat,
                                           const float* __restrict__ fw,
                                           const float* __restrict__ fb,
                                           const int* __restrict__ region,
                                           float* __restrict__ out)
{
    const int b = blockIdx.x;
    const int lane = threadIdx.x;
    const int r = region[b] & (R_ - 1);

    const float* fv = feat + (size_t)b * 128;
    const float* w0 = fw + ((size_t)r * 2 + 0) * 128;
    const float* w1 = fw + ((size_t)r * 2 + 1) * 128;

    float p0 = 0.0f, p1 = 0.0f;
#pragma unroll
    for (int i = lane; i < 128; i += 32) {
        const float f = fv[i];
        p0 = fmaf(f, w0[i], p0);
        p1 = fmaf(f, w1[i], p1);
    }
#pragma unroll
    for (int off = 16; off > 0; off >>= 1) {
        p0 += __shfl_down_sync(0xFFFFFFFFu, p0, off);
        p1 += __shfl_down_sync(0xFFFFFFFFu, p1, off);
    }
    if (lane == 0) {
        out[b * 2 + 0] = p0 + fb[r * 2 + 0];
        out[b * 2 + 1] = p1 + fb[r * 2 + 1];
    }
}

// ---------------------------------------------------------------------------
extern "C" void kernel_launch(void* const* d_in, const int* in_sizes, int n_in,
                              void* d_out, int out_size)
{
    const float* image  = (const float*)d_in[0];
    const int*   region = (const int*)d_in[1];
    const float* w1     = (const float*)d_in[2];
    const float* b1     = (const float*)d_in[3];
    const float* w2     = (const float*)d_in[4];
    const float* b2     = (const float*)d_in[5];
    const float* w3     = (const float*)d_in[6];
    const float* b3     = (const float*)d_in[7];
    const float* fw     = (const float*)d_in[8];
    const float* fb     = (const float*)d_in[9];
    float* out = (float*)d_out;

    float *buf1, *buf2, *buf3, *feat;
    cudaGetSymbolAddress((void**)&buf1, g_buf1);
    cudaGetSymbolAddress((void**)&buf2, g_buf2);
    cudaGetSymbolAddress((void**)&buf3, g_buf3);
    cudaGetSymbolAddress((void**)&feat, g_feat);

    // conv1: 3->32, HOUT=128. tiles = 64x32 = 2048 -> 8 blocks x 256; 2 ch groups
    conv_s2_v2<3, 32, 128, 256><<<dim3(8, 2, B_), 256>>>(image, w1, b1, region, buf1);
    // conv2: 32->64, HOUT=64. tiles = 32x16 = 512 -> 2 blocks x 256; 4 ch groups
    conv_s2_v2<32, 64, 64, 256><<<dim3(2, 4, B_), 256>>>(buf1, w2, b2, region, buf2);
    // conv3: 64->128, HOUT=32. tiles = 16x8 = 128 -> 1 block x 128; 8 ch groups
    conv_s2_v2<64, 128, 32, 128><<<dim3(1, 8, B_), 128>>>(buf2, w3, b3, region, buf3);
    // GAP: one block per (b, c)
    gap_k<<<B_ * 128, 256>>>(buf3, feat);
    // FC: one warp per sample
    fc_k<<<B_, 32>>>(feat, fw, fb, region, out);
}

// round 4
// speedup vs baseline: 1.8187x; 1.0290x over previous
#include <cuda_runtime.h>
#include <cuda_bf16.h>
#include <cstdint>

// ---------------------------------------------------------------------------
// RegionModel round-4: smem-tiled direct conv with packed f32x2 FMA.
// Per block: CB=16*NG output channels x (TPY x TPX) output pixels.
// Per thread: 16 channels (8 f32x2 pairs) x 4 px (strided by TPX/4).
// Input staged in smem per CC-channel chunk (zero-padded halo, no branches
// in the hot loop). Weights staged as packed pairs per chunk.
// ---------------------------------------------------------------------------

#define B_   128
#define R_   8

typedef unsigned long long u64;

__device__ float g_buf1[(size_t)B_ * 32 * 128 * 128];  // 256 MiB
__device__ float g_buf2[(size_t)B_ * 64 * 64 * 64];    // 128 MiB
__device__ float g_buf3[(size_t)B_ * 128 * 32 * 32];   //  64 MiB
__device__ float g_feat[(size_t)B_ * 128];

__device__ __forceinline__ u64 pack2(float lo, float hi) {
    u64 p; asm("mov.b64 %0, {%1, %2};" : "=l"(p) : "f"(lo), "f"(hi)); return p;
}
__device__ __forceinline__ u64 pack_dup(float x) {
    u64 p; asm("mov.b64 %0, {%1, %1};" : "=l"(p) : "f"(x)); return p;
}
__device__ __forceinline__ void unpack2(u64 p, float& lo, float& hi) {
    asm("mov.b64 {%0, %1}, %2;" : "=f"(lo), "=f"(hi) : "l"(p));
}
#define FFMA2(acc, x, w) \
    asm("fma.rn.f32x2 %0, %1, %2, %0;" : "+l"(acc) : "l"(x), "l"(w))

// ---------------------------------------------------------------------------
template <int CIN, int COUT, int HOUT, int TPY, int TPX, int CC, int BLK>
__global__ void __launch_bounds__(BLK, 2) conv_s2_v3(
    const float* __restrict__ in, const float* __restrict__ W,
    const float* __restrict__ Bias, const int* __restrict__ region,
    float* __restrict__ out)
{
    constexpr int HIN   = 2 * HOUT;
    constexpr int SPX   = TPX / 4;          // px stride / threads per row
    constexpr int PXT   = TPY * SPX;        // threads per channel-group
    constexpr int NG    = BLK / PXT;        // channel groups per block
    constexpr int CB    = 16 * NG;          // channels per block
    constexpr int ROWS  = 2 * TPY + 1;
    constexpr int COLS  = 2 * TPX + 1;
    constexpr int XSTR  = 2 * TPX + 9;      // smem row pitch (bank spread)
    constexpr int TILESX = HOUT / TPX;
    constexpr int XS_FLOATS = CC * ROWS * XSTR;
    constexpr int XS_AL  = ((XS_FLOATS * 4 + 15) & ~15);
    constexpr int NPAIR  = CB / 2;

    extern __shared__ char smem_raw[];
    float* xs = (float*)smem_raw;
    u64*   ws = (u64*)(smem_raw + XS_AL);

    const int tid    = threadIdx.x;
    const int b      = blockIdx.z;
    const int co0    = blockIdx.y * CB;
    const int tile_y = blockIdx.x / TILESX;
    const int tile_x = blockIdx.x % TILESX;
    const int r      = region[b] & (R_ - 1);

    const int g   = tid / PXT;              // channel group (0..NG-1)
    const int pt  = tid % PXT;
    const int row = pt / SPX;               // output row within tile
    const int tx  = pt % SPX;               // base output col within tile

    const int gy0 = 2 * (tile_y * TPY) - 1;
    const int gx0 = 2 * (tile_x * TPX) - 1;

    // bias init: 8 pairs x 4 px
    u64 acc[4][8];
#pragma unroll
    for (int c = 0; c < 8; c++) {
        const int ch = co0 + 16 * g + 2 * c;
        const u64 bp = pack2(Bias[r * COUT + ch], Bias[r * COUT + ch + 1]);
#pragma unroll
        for (int px = 0; px < 4; px++) acc[px][c] = bp;
    }

    const float* xb = in + (size_t)b * CIN * HIN * HIN;
    const float* wb = W + (size_t)r * COUT * CIN * 9;

    for (int ci0 = 0; ci0 < CIN; ci0 += CC) {
        __syncthreads();   // previous chunk's compute done
        // ---- stage input chunk (zero-padded) ----
        for (int idx = tid; idx < CC * ROWS * COLS; idx += BLK) {
            const int ci  = idx / (ROWS * COLS);
            const int rem = idx % (ROWS * COLS);
            const int rr  = rem / COLS;
            const int cc  = rem % COLS;
            const int gy  = gy0 + rr;
            const int gx  = gx0 + cc;
            float v = 0.0f;
            if ((unsigned)gy < (unsigned)HIN && (unsigned)gx < (unsigned)HIN)
                v = __ldg(xb + (size_t)(ci0 + ci) * HIN * HIN + (size_t)gy * HIN + gx);
            xs[(ci * ROWS + rr) * XSTR + cc] = v;
        }
        // ---- stage packed weights for this chunk ----
        for (int idx = tid; idx < CC * 9 * NPAIR; idx += BLK) {
            const int p  = idx % NPAIR;
            const int t2 = idx / NPAIR;           // ci*9 + tap
            const int ci = t2 / 9, tap = t2 % 9;
            const float lo = wb[((size_t)(co0 + 2 * p)     * CIN + ci0 + ci) * 9 + tap];
            const float hi = wb[((size_t)(co0 + 2 * p + 1) * CIN + ci0 + ci) * 9 + tap];
            ws[idx] = pack2(lo, hi);
        }
        __syncthreads();

        // ---- compute ----
#pragma unroll 1
        for (int ci = 0; ci < CC; ci++) {
#pragma unroll
            for (int ky = 0; ky < 3; ky++) {
#pragma unroll
                for (int kx = 0; kx < 3; kx++) {
                    const int tap = ky * 3 + kx;
                    u64 wv[8];
#pragma unroll
                    for (int c = 0; c < 8; c++)
                        wv[c] = ws[(ci * 9 + tap) * NPAIR + g * 8 + c];
                    const float* xr =
                        &xs[(ci * ROWS + 2 * row + ky) * XSTR + 2 * tx + kx];
#pragma unroll
                    for (int px = 0; px < 4; px++) {
                        const u64 xx = pack_dup(xr[px * 2 * SPX]);
#pragma unroll
                        for (int c = 0; c < 8; c++)
                            FFMA2(acc[px][c], xx, wv[c]);
                    }
                }
            }
        }
    }

    // ---- ReLU + store ----
    const int oy = tile_y * TPY + row;
#pragma unroll
    for (int c = 0; c < 8; c++) {
        const int ch = co0 + 16 * g + 2 * c;
        float* o0 = out + (((size_t)b * COUT + ch) * HOUT + oy) * HOUT;
        float* o1 = o0 + (size_t)HOUT * HOUT;
#pragma unroll
        for (int px = 0; px < 4; px++) {
            float lo, hi;
            unpack2(acc[px][c], lo, hi);
            const int ox = tile_x * TPX + tx + px * SPX;
            o0[ox] = fmaxf(lo, 0.0f);
            o1[ox] = fmaxf(hi, 0.0f);
        }
    }
}

// ---------------------------------------------------------------------------
__global__ void __launch_bounds__(256) gap_k(const float* __restrict__ in,
                                             float* __restrict__ feat)
{
    const int bc = blockIdx.x;
    const float* p = in + (size_t)bc * 1024;
    const int t = threadIdx.x;
    float s = p[t] + p[t + 256] + p[t + 512] + p[t + 768];
    __shared__ float red[256];
    red[t] = s;
    __syncthreads();
#pragma unroll
    for (int off = 128; off >= 32; off >>= 1) {
        if (t < off) red[t] += red[t + off];
        __syncthreads();
    }
    if (t < 32) {
        float v = red[t];
#pragma unroll
        for (int off = 16; off > 0; off >>= 1)
            v += __shfl_down_sync(0xFFFFFFFFu, v, off);
        if (t == 0) feat[bc] = v * (1.0f / 1024.0f);
    }
}

// ---------------------------------------------------------------------------
__global__ void __launch_bounds__(32) fc_k(const float* __restrict__ feat,
                                           const float* __restrict__ fw,
                                           const float* __restrict__ fb,
                                           const int* __restrict__ region,
                                           float* __restrict__ out)
{
    const int b = blockIdx.x;
    const int lane = threadIdx.x;
    const int r = region[b] & (R_ - 1);
    const float* fv = feat + (size_t)b * 128;
    const float* w0 = fw + ((size_t)r * 2 + 0) * 128;
    const float* w1 = fw + ((size_t)r * 2 + 1) * 128;
    float p0 = 0.0f, p1 = 0.0f;
#pragma unroll
    for (int i = lane; i < 128; i += 32) {
        const float f = fv[i];
        p0 = fmaf(f, w0[i], p0);
        p1 = fmaf(f, w1[i], p1);
    }
#pragma unroll
    for (int off = 16; off > 0; off >>= 1) {
        p0 += __shfl_down_sync(0xFFFFFFFFu, p0, off);
        p1 += __shfl_down_sync(0xFFFFFFFFu, p1, off);
    }
    if (lane == 0) {
        out[b * 2 + 0] = p0 + fb[r * 2 + 0];
        out[b * 2 + 1] = p1 + fb[r * 2 + 1];
    }
}

// ---------------------------------------------------------------------------
template <int CIN, int COUT, int HOUT, int TPY, int TPX, int CC, int BLK>
static inline int conv_smem_bytes() {
    constexpr int ROWS = 2 * TPY + 1;
    constexpr int XSTR = 2 * TPX + 9;
    constexpr int XS_AL = ((CC * ROWS * XSTR * 4 + 15) & ~15);
    constexpr int NG = BLK / (TPY * (TPX / 4));
    constexpr int NPAIR = (16 * NG) / 2;
    return XS_AL + CC * 9 * NPAIR * 8;
}

extern "C" void kernel_launch(void* const* d_in, const int* in_sizes, int n_in,
                              void* d_out, int out_size)
{
    const float* image  = (const float*)d_in[0];
    const int*   region = (const int*)d_in[1];
    const float* w1     = (const float*)d_in[2];
    const float* b1     = (const float*)d_in[3];
    const float* w2     = (const float*)d_in[4];
    const float* b2     = (const float*)d_in[5];
    const float* w3     = (const float*)d_in[6];
    const float* b3     = (const float*)d_in[7];
    const float* fw     = (const float*)d_in[8];
    const float* fb     = (const float*)d_in[9];
    float* out = (float*)d_out;

    float *buf1, *buf2, *buf3, *feat;
    cudaGetSymbolAddress((void**)&buf1, g_buf1);
    cudaGetSymbolAddress((void**)&buf2, g_buf2);
    cudaGetSymbolAddress((void**)&buf3, g_buf3);
    cudaGetSymbolAddress((void**)&feat, g_feat);

    // conv1: 3->32, HOUT=128, TPY=8, TPX=64 (16x2 tiles), CB=32 (grid.y=1)
    conv_s2_v3<3, 32, 128, 8, 64, 3, 256>
        <<<dim3(32, 1, B_), 256, conv_smem_bytes<3, 32, 128, 8, 64, 3, 256>()>>>
        (image, w1, b1, region, buf1);
    // conv2: 32->64, HOUT=64, TPY=16, TPX=32 (4x2 tiles), CB=32 (grid.y=2)
    conv_s2_v3<32, 64, 64, 16, 32, 4, 256>
        <<<dim3(8, 2, B_), 256, conv_smem_bytes<32, 64, 64, 16, 32, 4, 256>()>>>
        (buf1, w2, b2, region, buf2);
    // conv3: 64->128, HOUT=32, TPY=16, TPX=32 (2x1 tiles), CB=32 (grid.y=4)
    conv_s2_v3<64, 128, 32, 16, 32, 4, 256>
        <<<dim3(2, 4, B_), 256, conv_smem_bytes<64, 128, 32, 16, 32, 4, 256>()>>>
        (buf2, w3, b3, region, buf3);
    gap_k<<<B_ * 128, 256>>>(buf3, feat);
    fc_k<<<B_, 32>>>(feat, fw, fb, region, out);
}